// round 4
// baseline (speedup 1.0000x reference)
#include <cuda_runtime.h>

#define N_NODES 163842
#define N_EDGES 983040
#define SCAN_B  1024
#define SCAN_NB ((N_NODES + SCAN_B - 1) / SCAN_B)   // 161

// ---------------- scratch (device globals; no allocation allowed) ----------------
__device__ float d_xwm[(size_t)N_NODES * 192];   // x @ g   (3*Cout, dense rows)
__device__ float d_xwr[(size_t)N_NODES * 64];    // x @ root
__device__ float d_h0[(size_t)N_NODES * 64];
__device__ float d_h1[(size_t)N_NODES * 64];
__device__ float4 d_g4[3][N_EDGES];              // per-layer edge gaussians (CSR order)
__device__ float2 d_csr_ea[N_EDGES];
__device__ int   d_csr_src[N_EDGES];
__device__ int   d_src[N_EDGES];
__device__ int   d_dst[N_EDGES];
__device__ int   d_cnt[N_NODES];
__device__ int   d_incl[N_NODES];
__device__ int   d_rowptr[N_NODES + 1];
__device__ int   d_cursor[N_NODES];
__device__ int   d_bsum[SCAN_NB];
__device__ int   d_is64;

// ---------------- packed fp32x2 FMA (FFMA2) ----------------
__device__ __forceinline__ float2 ffma2(float2 a, float2 b, float2 c) {
    unsigned long long ra = *reinterpret_cast<unsigned long long*>(&a);
    unsigned long long rb = *reinterpret_cast<unsigned long long*>(&b);
    unsigned long long rc = *reinterpret_cast<unsigned long long*>(&c);
    unsigned long long rd;
    asm("fma.rn.f32x2 %0, %1, %2, %3;" : "=l"(rd) : "l"(ra), "l"(rb), "l"(rc));
    return *reinterpret_cast<float2*>(&rd);
}

// ---------------- edge index handling ----------------
__global__ void detect_kernel(const unsigned* ei) {
    if (threadIdx.x == 0) {
        int ok = 1;
        for (int i = 1; i < 64; i += 2)
            if (ei[i] != 0u) ok = 0;
        d_is64 = ok;
    }
}

__global__ void zero_cnt() {
    int i = blockIdx.x * blockDim.x + threadIdx.x;
    if (i < N_NODES) d_cnt[i] = 0;
}

__global__ void convert_hist(const void* eiv) {
    int e = blockIdx.x * blockDim.x + threadIdx.x;
    if (e >= N_EDGES) return;
    int s, d;
    if (d_is64) {
        const long long* ei = (const long long*)eiv;
        s = (int)ei[e]; d = (int)ei[N_EDGES + e];
    } else {
        const int* ei = (const int*)eiv;
        s = ei[e]; d = ei[N_EDGES + e];
    }
    d_src[e] = s;
    d_dst[e] = d;
    atomicAdd(&d_cnt[d], 1);
}

// ---------------- CSR build ----------------
__global__ void scan1() {
    __shared__ int s[2][SCAN_B];
    int t = threadIdx.x;
    int i = blockIdx.x * SCAN_B + t;
    int v = (i < N_NODES) ? d_cnt[i] : 0;
    s[0][t] = v;
    int cur = 0;
    for (int off = 1; off < SCAN_B; off <<= 1) {
        __syncthreads();
        int nv = s[cur][t] + (t >= off ? s[cur][t - off] : 0);
        s[cur ^ 1][t] = nv;
        cur ^= 1;
    }
    __syncthreads();
    if (i < N_NODES) d_incl[i] = s[cur][t];
    if (t == SCAN_B - 1) d_bsum[blockIdx.x] = s[cur][t];
}

__global__ void scan2() {   // parallel scan of the 161 block sums
    __shared__ int s[2][256];
    int t = threadIdx.x;
    int v = (t < SCAN_NB) ? d_bsum[t] : 0;
    s[0][t] = v;
    int cur = 0;
    for (int off = 1; off < 256; off <<= 1) {
        __syncthreads();
        int nv = s[cur][t] + (t >= off ? s[cur][t - off] : 0);
        s[cur ^ 1][t] = nv;
        cur ^= 1;
    }
    __syncthreads();
    if (t < SCAN_NB) d_bsum[t] = s[cur][t] - v;        // exclusive
    if (t == 255) d_rowptr[N_NODES] = s[cur][t];
}

__global__ void scan3() {
    int i = blockIdx.x * blockDim.x + threadIdx.x;
    if (i >= N_NODES) return;
    int excl = d_incl[i] - d_cnt[i] + d_bsum[i / SCAN_B];
    d_rowptr[i] = excl;
    d_cursor[i] = excl;
}

__global__ void fill_kernel(const float* __restrict__ ea) {
    int e = blockIdx.x * blockDim.x + threadIdx.x;
    if (e >= N_EDGES) return;
    int p = atomicAdd(&d_cursor[d_dst[e]], 1);
    d_csr_src[p] = d_src[e];
    d_csr_ea[p] = ((const float2*)ea)[e];
}

// ---------------- Gaussian weights, all 3 layers in one pass ----------------
__global__ void gauss_all(const float* __restrict__ mu0, const float* __restrict__ sg0,
                          const float* __restrict__ mu1, const float* __restrict__ sg1,
                          const float* __restrict__ mu2, const float* __restrict__ sg2) {
    int i = blockIdx.x * blockDim.x + threadIdx.x;
    if (i >= N_EDGES) return;
    float2 pc = d_csr_ea[i];
    const float* mus[3] = {mu0, mu1, mu2};
    const float* sgs[3] = {sg0, sg1, sg2};
#pragma unroll
    for (int l = 0; l < 3; l++) {
        float g[3];
#pragma unroll
        for (int k = 0; k < 3; k++) {
            float dd0 = pc.x - mus[l][2 * k];
            float dd1 = pc.y - mus[l][2 * k + 1];
            float s0 = sgs[l][2 * k], s1 = sgs[l][2 * k + 1];
            float q = dd0 * dd0 / (1e-15f + s0 * s0) + dd1 * dd1 / (1e-15f + s1 * s1);
            g[k] = __expf(-0.5f * q);
        }
        d_g4[l][i] = make_float4(g[0], g[1], g[2], 0.f);
    }
}

// ---------------- generalized f32x2 GEMM ------------------------------------------
// out cols: [0, 3*COUT) -> xwm (message weights), [3*COUT, M) -> xwr (root weights)
// M = NCH*128, block (32, 8), BN = 8*TN nodes per block.
template <int CIN, int CINP, int CC, int COUT, int NCH, int TN>
__global__ void __launch_bounds__(256) gemm_f2(const float* __restrict__ x,
                                               const float* __restrict__ g,
                                               const float* __restrict__ root,
                                               float* __restrict__ xwm,
                                               float* __restrict__ xwr) {
    constexpr int M = NCH * 128;
    constexpr int KM = 3 * COUT;
    constexpr int BN = 8 * TN;
    __shared__ __align__(16) float gs[CC * M];
    __shared__ __align__(16) float xs[BN * CINP];
    const int tx = threadIdx.x, ty = threadIdx.y;
    const int tid = ty * 32 + tx;
    const int n0 = blockIdx.x * BN;

    for (int i = tid; i < BN * CINP; i += 256) {
        int nn = i / CINP, c = i - nn * CINP;
        int n = n0 + nn;
        xs[i] = (c < CIN && n < N_NODES) ? x[(size_t)n * CIN + c] : 0.f;
    }

    float2 acc[TN][NCH * 2];
#pragma unroll
    for (int j = 0; j < TN; j++)
#pragma unroll
        for (int i = 0; i < NCH * 2; i++) acc[j][i] = make_float2(0.f, 0.f);

    const int nb = ty * TN;
    for (int c0 = 0; c0 < CINP; c0 += CC) {
        __syncthreads();
        for (int i = tid; i < CC * M; i += 256) {
            int r = i / M, col = i - r * M;
            int gr = c0 + r;
            float v = 0.f;
            if (gr < CIN)
                v = (col < KM) ? g[gr * KM + col] : root[gr * COUT + (col - KM)];
            gs[i] = v;
        }
        __syncthreads();
#pragma unroll
        for (int c4 = 0; c4 < CC; c4 += 4) {
            float4 xv[TN];
#pragma unroll
            for (int j = 0; j < TN; j++)
                xv[j] = *(const float4*)&xs[(nb + j) * CINP + c0 + c4];
#pragma unroll
            for (int q = 0; q < 4; q++) {
                float4 ga[NCH];
#pragma unroll
                for (int ch = 0; ch < NCH; ch++)
                    ga[ch] = *(const float4*)&gs[(c4 + q) * M + ch * 128 + tx * 4];
#pragma unroll
                for (int j = 0; j < TN; j++) {
                    float xc = ((const float*)&xv[j])[q];
                    float2 xb = make_float2(xc, xc);
#pragma unroll
                    for (int ch = 0; ch < NCH; ch++) {
                        acc[j][2 * ch]     = ffma2(make_float2(ga[ch].x, ga[ch].y), xb, acc[j][2 * ch]);
                        acc[j][2 * ch + 1] = ffma2(make_float2(ga[ch].z, ga[ch].w), xb, acc[j][2 * ch + 1]);
                    }
                }
            }
        }
    }

#pragma unroll
    for (int j = 0; j < TN; j++) {
        int n = n0 + nb + j;
        if (n >= N_NODES) continue;
#pragma unroll
        for (int ch = 0; ch < NCH; ch++) {
            int col = ch * 128 + tx * 4;
            float4 v = make_float4(acc[j][2 * ch].x, acc[j][2 * ch].y,
                                   acc[j][2 * ch + 1].x, acc[j][2 * ch + 1].y);
            if (col < KM) *(float4*)&xwm[(size_t)n * KM + col] = v;
            else          *(float4*)&xwr[(size_t)n * COUT + (col - KM)] = v;
        }
    }
}

// ---------------- gather + combine, Cout=32 (layer 0) ----------------
__global__ void gather32(const float* __restrict__ xwm,
                         const float* __restrict__ xwr,
                         const float* __restrict__ bias,
                         const float4* __restrict__ g4,
                         float* __restrict__ out) {
    int warp = (blockIdx.x * blockDim.x + threadIdx.x) >> 5;
    int lane = threadIdx.x & 31;
    if (warp >= N_NODES) return;
    int beg = d_rowptr[warp], end = d_rowptr[warp + 1];
    float a0 = 0.f;
#pragma unroll 2
    for (int i = beg; i < end; i++) {
        int s = d_csr_src[i];
        float4 gg = g4[i];
        const float* p = xwm + (size_t)s * 96;
        a0 += gg.x * p[lane] + gg.y * p[32 + lane] + gg.z * p[64 + lane];
    }
    float inv = 1.f / fmaxf((float)(end - beg), 1.f);
    float h = a0 * inv + xwr[(size_t)warp * 32 + lane] + bias[lane];
    out[(size_t)warp * 32 + lane] = fmaxf(h, 0.f);
}

// ---------------- gather + combine, Cout=64 (layers 1/2; layer2 fuses FC) -------
template <bool FINAL>
__global__ void gather64(const float* __restrict__ xwm,
                         const float* __restrict__ xwr,
                         const float* __restrict__ bias,
                         const float4* __restrict__ g4,
                         const float* __restrict__ fcw,
                         const float* __restrict__ fcb,
                         float* __restrict__ out) {
    int warp = (blockIdx.x * blockDim.x + threadIdx.x) >> 5;
    int lane = threadIdx.x & 31;
    if (warp >= N_NODES) return;
    int beg = d_rowptr[warp], end = d_rowptr[warp + 1];
    float a0 = 0.f, a1 = 0.f;
#pragma unroll 2
    for (int i = beg; i < end; i++) {
        int s = d_csr_src[i];
        float4 gg = g4[i];
        const float* p = xwm + (size_t)s * 192;
        a0 += gg.x * p[lane]      + gg.y * p[64 + lane] + gg.z * p[128 + lane];
        a1 += gg.x * p[32 + lane] + gg.y * p[96 + lane] + gg.z * p[160 + lane];
    }
    float inv = 1.f / fmaxf((float)(end - beg), 1.f);
    float h0 = fmaxf(a0 * inv + xwr[(size_t)warp * 64 + lane]      + bias[lane], 0.f);
    float h1 = fmaxf(a1 * inv + xwr[(size_t)warp * 64 + 32 + lane] + bias[32 + lane], 0.f);
    if (!FINAL) {
        out[(size_t)warp * 64 + lane] = h0;
        out[(size_t)warp * 64 + 32 + lane] = h1;
    } else {
        float p0 = h0 * fcw[2 * lane]     + h1 * fcw[2 * (lane + 32)];
        float p1 = h0 * fcw[2 * lane + 1] + h1 * fcw[2 * (lane + 32) + 1];
#pragma unroll
        for (int off = 16; off > 0; off >>= 1) {
            p0 += __shfl_xor_sync(0xffffffffu, p0, off);
            p1 += __shfl_xor_sync(0xffffffffu, p1, off);
        }
        if (lane == 0) {
            float l0 = p0 + fcb[0], l1 = p1 + fcb[1];
            float mx = fmaxf(l0, l1);
            float lse = mx + logf(expf(l0 - mx) + expf(l1 - mx));
            out[(size_t)warp * 2]     = l0 - lse;
            out[(size_t)warp * 2 + 1] = l1 - lse;
        }
    }
}

// ---------------- launch ----------------------------------------------------------
extern "C" void kernel_launch(void* const* d_in, const int* in_sizes, int n_in,
                              void* d_out, int out_size) {
    const float* x   = (const float*)d_in[0];
    const void*  ei  = d_in[1];
    const float* ea  = (const float*)d_in[2];
    const float* g[3]  = {(const float*)d_in[3],  (const float*)d_in[8],  (const float*)d_in[13]};
    const float* mu[3] = {(const float*)d_in[4],  (const float*)d_in[9],  (const float*)d_in[14]};
    const float* sg[3] = {(const float*)d_in[5],  (const float*)d_in[10], (const float*)d_in[15]};
    const float* rt[3] = {(const float*)d_in[6],  (const float*)d_in[11], (const float*)d_in[16]};
    const float* bi[3] = {(const float*)d_in[7],  (const float*)d_in[12], (const float*)d_in[17]};
    const float* fcw = (const float*)d_in[18];
    const float* fcb = (const float*)d_in[19];
    float* out = (float*)d_out;

    float *xwm, *xwr, *h0, *h1;
    float4* g4;
    cudaGetSymbolAddress((void**)&xwm, d_xwm);
    cudaGetSymbolAddress((void**)&xwr, d_xwr);
    cudaGetSymbolAddress((void**)&h0,  d_h0);
    cudaGetSymbolAddress((void**)&h1,  d_h1);
    cudaGetSymbolAddress((void**)&g4,  d_g4);

    const int EB = (N_EDGES + 255) / 256;
    const int NB = (N_NODES + 255) / 256;
    const int GW = (N_NODES * 32 + 255) / 256;     // warp-per-node grids
    const int GB = (N_NODES + 63) / 64;            // gemm grids (BN=64)

    // ---- CSR build (shared by all 3 layers) ----
    detect_kernel<<<1, 32>>>((const unsigned*)ei);
    zero_cnt<<<NB, 256>>>();
    convert_hist<<<EB, 256>>>(ei);
    scan1<<<SCAN_NB, SCAN_B>>>();
    scan2<<<1, 256>>>();
    scan3<<<NB, 256>>>();
    fill_kernel<<<EB, 256>>>(ea);
    gauss_all<<<EB, 256>>>(mu[0], sg[0], mu[1], sg[1], mu[2], sg[2]);

    // ---- layer 0: 22 -> 32 ----
    gemm_f2<22, 24, 24, 32, 1, 8><<<GB, dim3(32, 8)>>>(x, g[0], rt[0], xwm, xwr);
    gather32<<<GW, 256>>>(xwm, xwr, bi[0], g4, h0);

    // ---- layer 1: 32 -> 64 ----
    gemm_f2<32, 32, 32, 64, 2, 8><<<GB, dim3(32, 8)>>>(h0, g[1], rt[1], xwm, xwr);
    gather64<false><<<GW, 256>>>(xwm, xwr, bi[1], g4 + N_EDGES, fcw, fcb, h1);

    // ---- layer 2: 64 -> 64 (fused FC + log_softmax) ----
    gemm_f2<64, 64, 16, 64, 2, 8><<<GB, dim3(32, 8)>>>(h1, g[2], rt[2], xwm, xwr);
    gather64<true><<<GW, 256>>>(xwm, xwr, bi[2], g4 + 2 * (size_t)N_EDGES, fcw, fcb, out);
}

// round 6
// speedup vs baseline: 1.1960x; 1.1960x over previous
#include <cuda_runtime.h>

#define N_NODES 163842
#define N_EDGES 983040
#define SCAN_B  1024
#define SCAN_NB ((N_NODES + SCAN_B - 1) / SCAN_B)   // 161

// ---------------- scratch (device globals; no allocation allowed) ----------------
__device__ float d_xwm[(size_t)N_NODES * 192];   // x @ g   (3*Cout, dense rows)
__device__ float d_xwr[(size_t)N_NODES * 64];    // x @ root
__device__ float d_h0[(size_t)N_NODES * 64];
__device__ float d_h1[(size_t)N_NODES * 64];
__device__ float4 d_g4[3][N_EDGES];              // per-layer edge gaussians (CSR order)
__device__ float2 d_csr_ea[N_EDGES];
__device__ int   d_csr_src[N_EDGES];
__device__ int   d_src[N_EDGES];
__device__ int   d_dst[N_EDGES];
__device__ int   d_cnt[N_NODES];
__device__ int   d_incl[N_NODES];
__device__ int   d_rowptr[N_NODES + 1];
__device__ int   d_cursor[N_NODES];
__device__ int   d_bsum[SCAN_NB];
__device__ int   d_is64;

// ---------------- edge index handling ----------------
__global__ void detect_kernel(const unsigned* ei) {
    if (threadIdx.x == 0) {
        int ok = 1;
        for (int i = 1; i < 64; i += 2)
            if (ei[i] != 0u) ok = 0;
        d_is64 = ok;
    }
}

__global__ void zero_cnt() {
    int i = blockIdx.x * blockDim.x + threadIdx.x;
    if (i < N_NODES) d_cnt[i] = 0;
}

__global__ void convert_hist(const void* eiv) {
    int e = blockIdx.x * blockDim.x + threadIdx.x;
    if (e >= N_EDGES) return;
    int s, d;
    if (d_is64) {
        const long long* ei = (const long long*)eiv;
        s = (int)ei[e]; d = (int)ei[N_EDGES + e];
    } else {
        const int* ei = (const int*)eiv;
        s = ei[e]; d = ei[N_EDGES + e];
    }
    d_src[e] = s;
    d_dst[e] = d;
    atomicAdd(&d_cnt[d], 1);
}

// ---------------- CSR build ----------------
__global__ void scan1() {
    __shared__ int s[2][SCAN_B];
    int t = threadIdx.x;
    int i = blockIdx.x * SCAN_B + t;
    int v = (i < N_NODES) ? d_cnt[i] : 0;
    s[0][t] = v;
    int cur = 0;
    for (int off = 1; off < SCAN_B; off <<= 1) {
        __syncthreads();
        int nv = s[cur][t] + (t >= off ? s[cur][t - off] : 0);
        s[cur ^ 1][t] = nv;
        cur ^= 1;
    }
    __syncthreads();
    if (i < N_NODES) d_incl[i] = s[cur][t];
    if (t == SCAN_B - 1) d_bsum[blockIdx.x] = s[cur][t];
}

__global__ void scan2() {   // parallel scan of the 161 block sums
    __shared__ int s[2][256];
    int t = threadIdx.x;
    int v = (t < SCAN_NB) ? d_bsum[t] : 0;
    s[0][t] = v;
    int cur = 0;
    for (int off = 1; off < 256; off <<= 1) {
        __syncthreads();
        int nv = s[cur][t] + (t >= off ? s[cur][t - off] : 0);
        s[cur ^ 1][t] = nv;
        cur ^= 1;
    }
    __syncthreads();
    if (t < SCAN_NB) d_bsum[t] = s[cur][t] - v;        // exclusive
    if (t == 255) d_rowptr[N_NODES] = s[cur][t];
}

__global__ void scan3() {
    int i = blockIdx.x * blockDim.x + threadIdx.x;
    if (i >= N_NODES) return;
    int excl = d_incl[i] - d_cnt[i] + d_bsum[i / SCAN_B];
    d_rowptr[i] = excl;
    d_cursor[i] = excl;
}

__global__ void fill_kernel(const float* __restrict__ ea) {
    int e = blockIdx.x * blockDim.x + threadIdx.x;
    if (e >= N_EDGES) return;
    int p = atomicAdd(&d_cursor[d_dst[e]], 1);
    d_csr_src[p] = d_src[e];
    d_csr_ea[p] = ((const float2*)ea)[e];
}

// ---------------- Gaussian weights, all 3 layers in one pass ----------------
__global__ void gauss_all(const float* __restrict__ mu0, const float* __restrict__ sg0,
                          const float* __restrict__ mu1, const float* __restrict__ sg1,
                          const float* __restrict__ mu2, const float* __restrict__ sg2) {
    int i = blockIdx.x * blockDim.x + threadIdx.x;
    if (i >= N_EDGES) return;
    float2 pc = d_csr_ea[i];
    const float* mus[3] = {mu0, mu1, mu2};
    const float* sgs[3] = {sg0, sg1, sg2};
#pragma unroll
    for (int l = 0; l < 3; l++) {
        float g[3];
#pragma unroll
        for (int k = 0; k < 3; k++) {
            float dd0 = pc.x - mus[l][2 * k];
            float dd1 = pc.y - mus[l][2 * k + 1];
            float s0 = sgs[l][2 * k], s1 = sgs[l][2 * k + 1];
            float q = dd0 * dd0 / (1e-15f + s0 * s0) + dd1 * dd1 / (1e-15f + s1 * s1);
            g[k] = __expf(-0.5f * q);
        }
        d_g4[l][i] = make_float4(g[0], g[1], g[2], 0.f);
    }
}

// ---------------- GEMM (layer 0): M=128 = [96 msg | 32 root], K=22, scalar tile --
template <int CIN, int COUT, int BX, int TM, int TN, int BN>
__global__ void gemm_s(const float* __restrict__ x,
                       const float* __restrict__ g,
                       const float* __restrict__ root,
                       float* __restrict__ xwm, float* __restrict__ xwr) {
    constexpr int M = BX * TM;
    constexpr int KM = 3 * COUT;
    __shared__ float gs[CIN * M];
    __shared__ float xs[BN * CIN];
    const int tid = threadIdx.y * BX + threadIdx.x;
    const int NT = BX * 4;
    const int n0 = blockIdx.x * BN;

    for (int i = tid; i < BN * CIN; i += NT) {
        int gi = n0 * CIN + i;
        xs[i] = (gi < N_NODES * CIN) ? x[gi] : 0.f;
    }
    for (int i = tid; i < CIN * M; i += NT) {
        int r = i / M, col = i - r * M;
        gs[i] = (col < KM) ? g[r * KM + col] : root[r * COUT + (col - KM)];
    }
    __syncthreads();

    float acc[TN][TM];
#pragma unroll
    for (int j = 0; j < TN; j++)
#pragma unroll
        for (int i = 0; i < TM; i++) acc[j][i] = 0.f;

    const int nb = threadIdx.y * TN;
#pragma unroll
    for (int c = 0; c < CIN; c++) {
        float gv[TM], xv[TN];
#pragma unroll
        for (int i = 0; i < TM; i++) gv[i] = gs[c * M + threadIdx.x + i * BX];
#pragma unroll
        for (int j = 0; j < TN; j++) xv[j] = xs[(nb + j) * CIN + c];
#pragma unroll
        for (int j = 0; j < TN; j++)
#pragma unroll
            for (int i = 0; i < TM; i++) acc[j][i] += xv[j] * gv[i];
    }

#pragma unroll
    for (int j = 0; j < TN; j++) {
        int n = n0 + nb + j;
        if (n >= N_NODES) continue;
#pragma unroll
        for (int i = 0; i < TM; i++) {
            int col = threadIdx.x + i * BX;
            if (col < KM) xwm[(size_t)n * KM + col] = acc[j][i];
            else          xwr[(size_t)n * COUT + (col - KM)] = acc[j][i];
        }
    }
}

// ---------------- GEMM (layers 1/2): M=256 = [192 msg | 64 root], vectorized -----
template <int CIN, int CC, int TN>
__global__ void gemm_vec(const float* __restrict__ x,
                         const float* __restrict__ g,
                         const float* __restrict__ root,
                         float* __restrict__ xwm, float* __restrict__ xwr) {
    constexpr int M = 256, KM = 192, COUT = 64, BX = 32, BY = 8;
    constexpr int BN = BY * TN;
    __shared__ __align__(16) float gs[CC * M];
    __shared__ __align__(16) float xs[BN * CIN];
    const int tx = threadIdx.x, ty = threadIdx.y;
    const int tid = ty * BX + tx;
    constexpr int NT = BX * BY;
    const int n0 = blockIdx.x * BN;

    for (int i = tid; i < BN * CIN; i += NT) {
        int gi = n0 * CIN + i;
        xs[i] = (gi < N_NODES * CIN) ? x[gi] : 0.f;
    }

    float acc[TN][8];
#pragma unroll
    for (int j = 0; j < TN; j++)
#pragma unroll
        for (int i = 0; i < 8; i++) acc[j][i] = 0.f;

    const int nb = ty * TN;
    for (int c0 = 0; c0 < CIN; c0 += CC) {
        __syncthreads();
        for (int i = tid; i < CC * M; i += NT) {
            int r = i / M, col = i - r * M;
            int gr = c0 + r;
            gs[i] = (col < KM) ? g[gr * KM + col] : root[gr * COUT + (col - KM)];
        }
        __syncthreads();
#pragma unroll
        for (int c4 = 0; c4 < CC; c4 += 4) {
            float4 xv[TN];
#pragma unroll
            for (int j = 0; j < TN; j++)
                xv[j] = *(const float4*)&xs[(nb + j) * CIN + c0 + c4];
#pragma unroll
            for (int q = 0; q < 4; q++) {
                float4 ga = *(const float4*)&gs[(c4 + q) * M + tx * 4];
                float4 gb = *(const float4*)&gs[(c4 + q) * M + 128 + tx * 4];
#pragma unroll
                for (int j = 0; j < TN; j++) {
                    float xc = ((const float*)&xv[j])[q];
                    acc[j][0] += xc * ga.x; acc[j][1] += xc * ga.y;
                    acc[j][2] += xc * ga.z; acc[j][3] += xc * ga.w;
                    acc[j][4] += xc * gb.x; acc[j][5] += xc * gb.y;
                    acc[j][6] += xc * gb.z; acc[j][7] += xc * gb.w;
                }
            }
        }
    }

#pragma unroll
    for (int j = 0; j < TN; j++) {
        int n = n0 + nb + j;
        if (n >= N_NODES) continue;
        *(float4*)&xwm[(size_t)n * KM + tx * 4] =
            make_float4(acc[j][0], acc[j][1], acc[j][2], acc[j][3]);
        int col = 128 + tx * 4;
        float4 v = make_float4(acc[j][4], acc[j][5], acc[j][6], acc[j][7]);
        if (col < KM) *(float4*)&xwm[(size_t)n * KM + col] = v;
        else          *(float4*)&xwr[(size_t)n * COUT + (col - KM)] = v;
    }
}

// ---------------- gather + combine, Cout=32 (layer 0) ----------------
__global__ void gather32(const float* __restrict__ xwm,
                         const float* __restrict__ xwr,
                         const float* __restrict__ bias,
                         const float4* __restrict__ g4,
                         float* __restrict__ out) {
    int warp = (blockIdx.x * blockDim.x + threadIdx.x) >> 5;
    int lane = threadIdx.x & 31;
    if (warp >= N_NODES) return;
    int beg = d_rowptr[warp], end = d_rowptr[warp + 1];
    float a0 = 0.f;
    for (int i = beg; i < end; i++) {
        int s = d_csr_src[i];
        float4 gg = g4[i];
        const float* p = xwm + (size_t)s * 96;
        a0 += gg.x * p[lane] + gg.y * p[32 + lane] + gg.z * p[64 + lane];
    }
    float inv = 1.f / fmaxf((float)(end - beg), 1.f);
    float h = a0 * inv + xwr[(size_t)warp * 32 + lane] + bias[lane];
    out[(size_t)warp * 32 + lane] = fmaxf(h, 0.f);
}

// ---------------- gather + combine, Cout=64 (layers 1/2; layer2 fuses FC) -------
template <bool FINAL>
__global__ void gather64(const float* __restrict__ xwm,
                         const float* __restrict__ xwr,
                         const float* __restrict__ bias,
                         const float4* __restrict__ g4,
                         const float* __restrict__ fcw,
                         const float* __restrict__ fcb,
                         float* __restrict__ out) {
    int warp = (blockIdx.x * blockDim.x + threadIdx.x) >> 5;
    int lane = threadIdx.x & 31;
    if (warp >= N_NODES) return;
    int beg = d_rowptr[warp], end = d_rowptr[warp + 1];
    float a0 = 0.f, a1 = 0.f;
    for (int i = beg; i < end; i++) {
        int s = d_csr_src[i];
        float4 gg = g4[i];
        const float* p = xwm + (size_t)s * 192;
        a0 += gg.x * p[lane]      + gg.y * p[64 + lane] + gg.z * p[128 + lane];
        a1 += gg.x * p[32 + lane] + gg.y * p[96 + lane] + gg.z * p[160 + lane];
    }
    float inv = 1.f / fmaxf((float)(end - beg), 1.f);
    float h0 = fmaxf(a0 * inv + xwr[(size_t)warp * 64 + lane]      + bias[lane], 0.f);
    float h1 = fmaxf(a1 * inv + xwr[(size_t)warp * 64 + 32 + lane] + bias[32 + lane], 0.f);
    if (!FINAL) {
        out[(size_t)warp * 64 + lane] = h0;
        out[(size_t)warp * 64 + 32 + lane] = h1;
    } else {
        float p0 = h0 * fcw[2 * lane]     + h1 * fcw[2 * (lane + 32)];
        float p1 = h0 * fcw[2 * lane + 1] + h1 * fcw[2 * (lane + 32) + 1];
#pragma unroll
        for (int off = 16; off > 0; off >>= 1) {
            p0 += __shfl_xor_sync(0xffffffffu, p0, off);
            p1 += __shfl_xor_sync(0xffffffffu, p1, off);
        }
        if (lane == 0) {
            float l0 = p0 + fcb[0], l1 = p1 + fcb[1];
            float mx = fmaxf(l0, l1);
            float lse = mx + logf(expf(l0 - mx) + expf(l1 - mx));
            out[(size_t)warp * 2]     = l0 - lse;
            out[(size_t)warp * 2 + 1] = l1 - lse;
        }
    }
}

// ---------------- launch ----------------------------------------------------------
extern "C" void kernel_launch(void* const* d_in, const int* in_sizes, int n_in,
                              void* d_out, int out_size) {
    const float* x   = (const float*)d_in[0];
    const void*  ei  = d_in[1];
    const float* ea  = (const float*)d_in[2];
    const float* g[3]  = {(const float*)d_in[3],  (const float*)d_in[8],  (const float*)d_in[13]};
    const float* mu[3] = {(const float*)d_in[4],  (const float*)d_in[9],  (const float*)d_in[14]};
    const float* sg[3] = {(const float*)d_in[5],  (const float*)d_in[10], (const float*)d_in[15]};
    const float* rt[3] = {(const float*)d_in[6],  (const float*)d_in[11], (const float*)d_in[16]};
    const float* bi[3] = {(const float*)d_in[7],  (const float*)d_in[12], (const float*)d_in[17]};
    const float* fcw = (const float*)d_in[18];
    const float* fcb = (const float*)d_in[19];
    float* out = (float*)d_out;

    float *xwm, *xwr, *h0, *h1;
    float4* g4;
    cudaGetSymbolAddress((void**)&xwm, d_xwm);
    cudaGetSymbolAddress((void**)&xwr, d_xwr);
    cudaGetSymbolAddress((void**)&h0,  d_h0);
    cudaGetSymbolAddress((void**)&h1,  d_h1);
    cudaGetSymbolAddress((void**)&g4,  d_g4);

    const int EB = (N_EDGES + 255) / 256;
    const int NB = (N_NODES + 255) / 256;
    const int GW = (N_NODES * 32 + 255) / 256;     // warp-per-node grids

    // ---- CSR build (shared by all 3 layers) ----
    detect_kernel<<<1, 32>>>((const unsigned*)ei);
    zero_cnt<<<NB, 256>>>();
    convert_hist<<<EB, 256>>>(ei);
    scan1<<<SCAN_NB, SCAN_B>>>();
    scan2<<<1, 256>>>();
    scan3<<<NB, 256>>>();
    fill_kernel<<<EB, 256>>>(ea);
    gauss_all<<<EB, 256>>>(mu[0], sg[0], mu[1], sg[1], mu[2], sg[2]);

    // ---- layer 0: 22 -> 32 ----
    gemm_s<22, 32, 32, 4, 4, 16><<<(N_NODES + 15) / 16, dim3(32, 4)>>>(x, g[0], rt[0], xwm, xwr);
    gather32<<<GW, 256>>>(xwm, xwr, bi[0], g4, h0);

    // ---- layer 1: 32 -> 64 ----
    gemm_vec<32, 32, 4><<<(N_NODES + 31) / 32, dim3(32, 8)>>>(h0, g[1], rt[1], xwm, xwr);
    gather64<false><<<GW, 256>>>(xwm, xwr, bi[1], g4 + N_EDGES, fcw, fcb, h1);

    // ---- layer 2: 64 -> 64 (fused FC + log_softmax) ----
    gemm_vec<64, 32, 4><<<(N_NODES + 31) / 32, dim3(32, 8)>>>(h1, g[2], rt[2], xwm, xwr);
    gather64<true><<<GW, 256>>>(xwm, xwr, bi[2], g4 + 2 * (size_t)N_EDGES, fcw, fcb, out);
}